// round 13
// baseline (speedup 1.0000x reference)
#include <cuda_runtime.h>
#include <cstdint>
#include <math.h>

// Problem constants
#define NC   64
#define NG   8
#define GS   32
#define IN_CH 2048
#define OUT_CH 256
#define NP   5
#define ROWS (NC*NG*GS)      // 16384
#define GN   (NG*GS)         // 256 rows per class
#define INV_SQRT_O 0.0625f   // 1/sqrt(256)

// ---------------- scratch (device globals; no allocation allowed) ----------------
__device__ float g_e    [(size_t)ROWS * OUT_CH];
__device__ float g_ctx  [(size_t)ROWS * IN_CH];      // tf32, k-permuted (GEMM3 A)
__device__ float g_feats[(size_t)ROWS * IN_CH];      // fp32 (residual/output path)
__device__ float g_ftf  [(size_t)ROWS * IN_CH];      // tf32, k-permuted (GEMM4 A)
__device__ float g_fae  [(size_t)ROWS * OUT_CH];
__device__ float g_pe   [(size_t)NC * NP * OUT_CH];
__device__ float g_att2 [(size_t)NC * NP * GN];
__device__ float g_ttf  [(size_t)IN_CH * IN_CH];     // trans, tf32 permuted
__device__ float g_w1tf [(size_t)OUT_CH * IN_CH];
__device__ float g_iw1tf[(size_t)OUT_CH * IN_CH];
__device__ float g_iw2tf[(size_t)OUT_CH * IN_CH];

// ======================= helpers (family-portable PTX only) ======================
__device__ __forceinline__ uint32_t smem_u32(const void* p) {
    uint32_t a;
    asm("{ .reg .u64 t; cvta.to.shared.u64 t, %1; cvt.u32.u64 %0, t; }" : "=r"(a) : "l"(p));
    return a;
}
__device__ __forceinline__ uint32_t f2tf32(float x) {
    uint32_t y;
    asm("cvt.rna.tf32.f32 %0, %1;" : "=r"(y) : "f"(x));
    return y;
}
// permuted offset within the row: 8-group stored in k-order {0,4,1,5,2,6,3,7}
__device__ __forceinline__ int permo(int k) {
    int j = k & 7;
    return (k & ~7) + ((j < 4) ? (j << 1) : (((j - 4) << 1) | 1));
}
#define CP_ASYNC16(dst, src) \
    asm volatile("cp.async.cg.shared.global [%0], [%1], 16;" :: "r"(dst), "l"(src) : "memory")
#define CP_COMMIT()  asm volatile("cp.async.commit_group;" ::: "memory")
#define CP_WAIT2()   asm volatile("cp.async.wait_group 2;" ::: "memory")

__device__ __forceinline__ void mma_tf32(float* c, const uint32_t* a, const uint32_t* b) {
    asm volatile(
        "mma.sync.aligned.m16n8k8.row.col.f32.tf32.tf32.f32 "
        "{%0,%1,%2,%3}, {%4,%5,%6,%7}, {%8,%9}, {%0,%1,%2,%3};"
        : "+f"(c[0]), "+f"(c[1]), "+f"(c[2]), "+f"(c[3])
        : "r"(a[0]), "r"(a[1]), "r"(a[2]), "r"(a[3]), "r"(b[0]), "r"(b[1]));
}

// ---------------------------------------------------------------------------------
// elementwise: dst[row][permo(k)] = tf32(src[row][k])   (row length IN_CH)
// ---------------------------------------------------------------------------------
__global__ void __launch_bounds__(256)
conv_perm(const float* __restrict__ src, float* __restrict__ dst, int n)
{
    int i = blockIdx.x * 256 + threadIdx.x;
    if (i < n) {
        int row = i >> 11;               // /IN_CH
        int k   = i & (IN_CH - 1);
        dst[((size_t)row << 11) + permo(k)] = __uint_as_float(f2tf32(src[i]));
    }
}

// ---------------------------------------------------------------------------------
// tf32 mma.sync GEMM: C[M,N] = A[M,K] * B[N,K]^T  (row-major, K contiguous)
// BM=BN=128, BK=16, 256 threads (8 warps 4m x 2n, warp 32x64), 4-stage cp.async.
// B is ALWAYS pre-converted tf32 + k-permuted.
// APRE=1: A likewise (vector fragment loads). APRE=0: raw fp32 A, scalar LDS + cvt.
// EPI=1: C = X + relu(acc), and also write FT[permuted] = tf32(C).
// ---------------------------------------------------------------------------------
#define SROW   20
#define STG_F  (2 * 128 * SROW)          // floats per stage (A+B)
#define SM_GEMM_BYTES (4 * STG_F * 4)    // 81920

template<int APRE, int EPI>
__global__ void __launch_bounds__(256, 2)
mgemm(const float* __restrict__ A, const float* __restrict__ B,
      float* __restrict__ C, const float* __restrict__ X,
      float* __restrict__ FT, int M, int N, int K)
{
    extern __shared__ float sm[];
    const int tid  = threadIdx.x;
    const int wid  = tid >> 5;
    const int lane = tid & 31;
    const int g    = lane >> 2;          // 0..7
    const int tig  = lane & 3;           // 0..3
    const int wm   = wid & 3;            // warp m index
    const int wn   = wid >> 2;           // warp n index
    const int bm   = blockIdx.y * 128;
    const int bn   = blockIdx.x * 128;
    const int KT   = K >> 4;

    // ---- global->smem copy setup: 2x16B of A + 2x16B of B per thread per stage
    const int lr = tid >> 2;             // 0..63
    const int lc = (tid & 3) << 2;       // 0,4,8,12
    int gr0 = bm + lr;      if (gr0 > M - 1) gr0 = M - 1;
    int gr1 = bm + lr + 64; if (gr1 > M - 1) gr1 = M - 1;
    const float* a0p = A + (size_t)gr0 * K + lc;
    const float* a1p = A + (size_t)gr1 * K + lc;
    const float* b0p = B + (size_t)(bn + lr)      * K + lc;
    const float* b1p = B + (size_t)(bn + lr + 64) * K + lc;

    const uint32_t sbase  = smem_u32(sm);
    const uint32_t doffA0 = (uint32_t)((lr      * SROW + lc) * 4);
    const uint32_t doffA1 = (uint32_t)(((lr+64) * SROW + lc) * 4);
    const uint32_t stgB   = 128 * SROW * 4;

    float acc[2][8][4];
#pragma unroll
    for (int mt = 0; mt < 2; mt++)
#pragma unroll
        for (int nt = 0; nt < 8; nt++)
#pragma unroll
            for (int q = 0; q < 4; q++) acc[mt][nt][q] = 0.f;

    // ---- prologue: 3 stages in flight
#pragma unroll
    for (int p = 0; p < 3; p++) {
        const uint32_t sb = sbase + p * (STG_F * 4);
        const int k0 = p * 16;
        CP_ASYNC16(sb + doffA0,        a0p + k0);
        CP_ASYNC16(sb + doffA1,        a1p + k0);
        CP_ASYNC16(sb + stgB + doffA0, b0p + k0);
        CP_ASYNC16(sb + stgB + doffA1, b1p + k0);
        CP_COMMIT();
    }

    for (int it = 0; it < KT; ++it) {
        CP_WAIT2();
        __syncthreads();

        const int s = it & 3;
        const float* As = sm + s * STG_F;
        const float* Bs = As + 128 * SROW;

#pragma unroll
        for (int kk = 0; kk < 16; kk += 8) {
            uint32_t af[2][4];
#pragma unroll
            for (int mt = 0; mt < 2; mt++) {
                const int m = wm * 32 + mt * 16;
                if (APRE) {
                    float2 v0 = *(const float2*)&As[(m + g    ) * SROW + kk + 2 * tig];
                    float2 v1 = *(const float2*)&As[(m + g + 8) * SROW + kk + 2 * tig];
                    af[mt][0] = __float_as_uint(v0.x);
                    af[mt][1] = __float_as_uint(v1.x);
                    af[mt][2] = __float_as_uint(v0.y);
                    af[mt][3] = __float_as_uint(v1.y);
                } else {
                    af[mt][0] = f2tf32(As[(m + g    ) * SROW + kk + tig    ]);
                    af[mt][1] = f2tf32(As[(m + g + 8) * SROW + kk + tig    ]);
                    af[mt][2] = f2tf32(As[(m + g    ) * SROW + kk + tig + 4]);
                    af[mt][3] = f2tf32(As[(m + g + 8) * SROW + kk + tig + 4]);
                }
            }
            uint32_t bf[8][2];
#pragma unroll
            for (int nt = 0; nt < 8; nt++) {
                const int n = wn * 64 + nt * 8;
                float2 v = *(const float2*)&Bs[(n + g) * SROW + kk + 2 * tig];
                bf[nt][0] = __float_as_uint(v.x);
                bf[nt][1] = __float_as_uint(v.y);
            }
#pragma unroll
            for (int mt = 0; mt < 2; mt++)
#pragma unroll
                for (int nt = 0; nt < 8; nt++)
                    mma_tf32(acc[mt][nt], af[mt], bf[nt]);
        }

        __syncthreads();
        if (it + 3 < KT) {
            const int ps = (it + 3) & 3;
            const uint32_t sb = sbase + ps * (STG_F * 4);
            const int k0 = (it + 3) * 16;
            CP_ASYNC16(sb + doffA0,        a0p + k0);
            CP_ASYNC16(sb + doffA1,        a1p + k0);
            CP_ASYNC16(sb + stgB + doffA0, b0p + k0);
            CP_ASYNC16(sb + stgB + doffA1, b1p + k0);
        }
        CP_COMMIT();
    }

    // ---- epilogue
#pragma unroll
    for (int mt = 0; mt < 2; mt++) {
        const int r0 = bm + wm * 32 + mt * 16 + g;
        const int r1 = r0 + 8;
#pragma unroll
        for (int nt = 0; nt < 8; nt++) {
            const int col = bn + wn * 64 + nt * 8 + 2 * tig;
            if (r0 < M) {
                float v0 = acc[mt][nt][0], v1 = acc[mt][nt][1];
                if (EPI) {
                    const float2 x = *(const float2*)(X + (size_t)r0 * N + col);
                    v0 = x.x + fmaxf(v0, 0.f);
                    v1 = x.y + fmaxf(v1, 0.f);
                    FT[(size_t)r0 * N + permo(col)]     = __uint_as_float(f2tf32(v0));
                    FT[(size_t)r0 * N + permo(col + 1)] = __uint_as_float(f2tf32(v1));
                }
                *(float2*)(C + (size_t)r0 * N + col) = make_float2(v0, v1);
            }
            if (r1 < M) {
                float v2 = acc[mt][nt][2], v3 = acc[mt][nt][3];
                if (EPI) {
                    const float2 x = *(const float2*)(X + (size_t)r1 * N + col);
                    v2 = x.x + fmaxf(v2, 0.f);
                    v3 = x.y + fmaxf(v3, 0.f);
                    FT[(size_t)r1 * N + permo(col)]     = __uint_as_float(f2tf32(v2));
                    FT[(size_t)r1 * N + permo(col + 1)] = __uint_as_float(f2tf32(v3));
                }
                *(float2*)(C + (size_t)r1 * N + col) = make_float2(v2, v3);
            }
        }
    }
}

// ---------------------------------------------------------------------------------
// Inner attention, fused: per (c,g) block b (512 blocks, 256 threads)
// ctx is written tf32-rounded + k-permuted (it only feeds GEMM3's A operand).
// ---------------------------------------------------------------------------------
#define EST 257
__global__ void __launch_bounds__(256)
inner_attn_kernel(const float* __restrict__ e, const float* __restrict__ X,
                  float* __restrict__ ctx)
{
    const int b   = blockIdx.x;
    const int tid = threadIdx.x;
    __shared__ float se[GS * EST];
    __shared__ float satt[GS * 33];

    const float* eb = e + (size_t)b * GS * OUT_CH;
    for (int i = tid; i < GS * OUT_CH; i += 256)
        se[(i >> 8) * EST + (i & 255)] = eb[i];
    __syncthreads();

    {
        const int n  = tid >> 3;
        const int m0 = (tid & 7) << 2;
        const float* en  = &se[n * EST];
        const float* em0 = &se[(m0 + 0) * EST];
        const float* em1 = &se[(m0 + 1) * EST];
        const float* em2 = &se[(m0 + 2) * EST];
        const float* em3 = &se[(m0 + 3) * EST];
        float s0 = 0.f, s1 = 0.f, s2 = 0.f, s3 = 0.f;
#pragma unroll 8
        for (int k = 0; k < OUT_CH; k++) {
            float a = en[k];
            s0 += a * em0[k]; s1 += a * em1[k]; s2 += a * em2[k]; s3 += a * em3[k];
        }
        satt[n * 33 + m0 + 0] = s0 * INV_SQRT_O;
        satt[n * 33 + m0 + 1] = s1 * INV_SQRT_O;
        satt[n * 33 + m0 + 2] = s2 * INV_SQRT_O;
        satt[n * 33 + m0 + 3] = s3 * INV_SQRT_O;
    }
    __syncthreads();

    if (tid < GS) {
        float mx = -1e30f;
#pragma unroll
        for (int m = 0; m < GS; m++) mx = fmaxf(mx, satt[tid * 33 + m]);
        float sum = 0.f;
#pragma unroll
        for (int m = 0; m < GS; m++) {
            float v = expf(satt[tid * 33 + m] - mx);
            satt[tid * 33 + m] = v; sum += v;
        }
        float inv = 1.f / sum;
#pragma unroll
        for (int m = 0; m < GS; m++) satt[tid * 33 + m] *= inv;
    }
    __syncthreads();

    const float* xb = X   + (size_t)b * GS * IN_CH;
    float*       cb = ctx + (size_t)b * GS * IN_CH;
    for (int d = tid; d < IN_CH; d += 256) {
        float acc[GS];
#pragma unroll
        for (int n = 0; n < GS; n++) acc[n] = 0.f;
#pragma unroll 4
        for (int m = 0; m < GS; m++) {
            float xv = xb[(size_t)m * IN_CH + d];
#pragma unroll
            for (int n = 0; n < GS; n++) acc[n] += satt[n * 33 + m] * xv;
        }
        const int od = permo(d);
#pragma unroll
        for (int n = 0; n < GS; n++)
            cb[(size_t)n * IN_CH + od] = __uint_as_float(f2tf32(acc[n]));
    }
}

// ---------------------------------------------------------------------------------
// Inter attention logits + softmax: per class c
// ---------------------------------------------------------------------------------
__global__ void __launch_bounds__(256)
inter_attn_kernel(const float* __restrict__ pe, const float* __restrict__ fae,
                  float* __restrict__ att2)
{
    const int c    = blockIdx.x;
    const int tid  = threadIdx.x;
    const int lane = tid & 31;
    const int w    = tid >> 5;
    __shared__ float spe[NP * OUT_CH];
    __shared__ float sl [NP * GN];

    for (int i = tid; i < NP * OUT_CH; i += 256)
        spe[i] = pe[(size_t)c * NP * OUT_CH + i];
    __syncthreads();

    for (int n = w; n < GN; n += 8) {
        const float* fr = fae + ((size_t)c * GN + n) * OUT_CH;
        float acc[NP] = {0.f, 0.f, 0.f, 0.f, 0.f};
        for (int k = lane; k < OUT_CH; k += 32) {
            float f = fr[k];
#pragma unroll
            for (int p = 0; p < NP; p++) acc[p] += spe[p * OUT_CH + k] * f;
        }
#pragma unroll
        for (int p = 0; p < NP; p++) {
#pragma unroll
            for (int off = 16; off; off >>= 1)
                acc[p] += __shfl_xor_sync(0xffffffffu, acc[p], off);
            if (lane == 0) sl[p * GN + n] = acc[p] * INV_SQRT_O;
        }
    }
    __syncthreads();

    if (w < NP) {
        float mx = -1e30f;
        for (int n = lane; n < GN; n += 32) mx = fmaxf(mx, sl[w * GN + n]);
#pragma unroll
        for (int off = 16; off; off >>= 1)
            mx = fmaxf(mx, __shfl_xor_sync(0xffffffffu, mx, off));
        float sum = 0.f;
        for (int n = lane; n < GN; n += 32) {
            float v = expf(sl[w * GN + n] - mx);
            sl[w * GN + n] = v; sum += v;
        }
#pragma unroll
        for (int off = 16; off; off >>= 1)
            sum += __shfl_xor_sync(0xffffffffu, sum, off);
        float inv = 1.f / sum;
        for (int n = lane; n < GN; n += 32)
            att2[(size_t)c * NP * GN + w * GN + n] = sl[w * GN + n] * inv;
    }
}

// ---------------------------------------------------------------------------------
// Output gather: out[c,p,d] = sum_n att2[c,p,n] * feats[c,n,d]
// ---------------------------------------------------------------------------------
__global__ void __launch_bounds__(256)
out_kernel(const float* __restrict__ att2, const float* __restrict__ feats,
           float* __restrict__ out)
{
    const int c = blockIdx.x;
    const int d = blockIdx.y * 256 + threadIdx.x;
    __shared__ float sa[NP * GN];
    for (int i = threadIdx.x; i < NP * GN; i += 256)
        sa[i] = att2[(size_t)c * NP * GN + i];
    __syncthreads();

    const float* fb = feats + (size_t)c * GN * IN_CH + d;
    float acc[NP] = {0.f, 0.f, 0.f, 0.f, 0.f};
#pragma unroll 4
    for (int n = 0; n < GN; n++) {
        float f = fb[(size_t)n * IN_CH];
#pragma unroll
        for (int p = 0; p < NP; p++) acc[p] += sa[p * GN + n] * f;
    }
#pragma unroll
    for (int p = 0; p < NP; p++)
        out[((size_t)c * NP + p) * IN_CH + d] = acc[p];
}

// ---------------------------------------------------------------------------------
extern "C" void kernel_launch(void* const* d_in, const int* in_sizes, int n_in,
                              void* d_out, int out_size)
{
    const float* topk   = (const float*)d_in[0];  // [64,8,32,2048]
    const float* protos = (const float*)d_in[1];  // [64,5,2048]
    const float* w1     = (const float*)d_in[2];  // [256,2048]
    const float* trans  = (const float*)d_in[3];  // [2048,2048]
    const float* iw1    = (const float*)d_in[4];  // [256,2048]
    const float* iw2    = (const float*)d_in[5];  // [256,2048]
    float* out = (float*)d_out;

    float *e, *ctx, *feats, *ftf, *fae, *pe, *att2, *ttf, *w1tf, *iw1tf, *iw2tf;
    cudaGetSymbolAddress((void**)&e,     g_e);
    cudaGetSymbolAddress((void**)&ctx,   g_ctx);
    cudaGetSymbolAddress((void**)&feats, g_feats);
    cudaGetSymbolAddress((void**)&ftf,   g_ftf);
    cudaGetSymbolAddress((void**)&fae,   g_fae);
    cudaGetSymbolAddress((void**)&pe,    g_pe);
    cudaGetSymbolAddress((void**)&att2,  g_att2);
    cudaGetSymbolAddress((void**)&ttf,   g_ttf);
    cudaGetSymbolAddress((void**)&w1tf,  g_w1tf);
    cudaGetSymbolAddress((void**)&iw1tf, g_iw1tf);
    cudaGetSymbolAddress((void**)&iw2tf, g_iw2tf);

    cudaFuncSetAttribute(mgemm<0,0>, cudaFuncAttributeMaxDynamicSharedMemorySize, SM_GEMM_BYTES);
    cudaFuncSetAttribute(mgemm<1,0>, cudaFuncAttributeMaxDynamicSharedMemorySize, SM_GEMM_BYTES);
    cudaFuncSetAttribute(mgemm<1,1>, cudaFuncAttributeMaxDynamicSharedMemorySize, SM_GEMM_BYTES);

    // 0) pre-convert all B operands to tf32 + k-permuted layout
    conv_perm<<<(OUT_CH * IN_CH) / 256, 256>>>(w1,    w1tf,  OUT_CH * IN_CH);
    conv_perm<<<(OUT_CH * IN_CH) / 256, 256>>>(iw1,   iw1tf, OUT_CH * IN_CH);
    conv_perm<<<(OUT_CH * IN_CH) / 256, 256>>>(iw2,   iw2tf, OUT_CH * IN_CH);
    conv_perm<<<(IN_CH * IN_CH) / 256, 256>>>(trans, ttf,   IN_CH * IN_CH);

    // 1) e = X @ inner_w1^T                [16384,256]   (raw A)
    mgemm<0,0><<<dim3(OUT_CH / 128, ROWS / 128), 256, SM_GEMM_BYTES>>>(
        topk, w1tf, e, nullptr, nullptr, ROWS, OUT_CH, IN_CH);
    // 2) inner attention (S, softmax, ctx) fused; ctx written tf32+permuted
    inner_attn_kernel<<<NC * NG, 256>>>(e, topk, ctx);
    // 3) feats = X + relu(ctx @ trans^T)   [16384,2048]  (APRE, epi writes ftf)
    mgemm<1,1><<<dim3(IN_CH / 128, ROWS / 128), 256, SM_GEMM_BYTES>>>(
        ctx, ttf, feats, topk, ftf, ROWS, IN_CH, IN_CH);
    // 4) fa_e = feats @ inter_w1^T         [16384,256]   (APRE via ftf)
    mgemm<1,0><<<dim3(OUT_CH / 128, ROWS / 128), 256, SM_GEMM_BYTES>>>(
        ftf, iw1tf, fae, nullptr, nullptr, ROWS, OUT_CH, IN_CH);
    // 5) p_e = protos @ inter_w2^T         [320,256]     (raw A)
    mgemm<0,0><<<dim3(OUT_CH / 128, (NC * NP + 127) / 128), 256, SM_GEMM_BYTES>>>(
        protos, iw2tf, pe, nullptr, nullptr, NC * NP, OUT_CH, IN_CH);
    // 6) inter attention logits + softmax
    inter_attn_kernel<<<NC, 256>>>(pe, fae, att2);
    // 7) out = att2 @ feats_all            [64,5,2048]
    out_kernel<<<dim3(NC, IN_CH / 256), 256>>>(att2, feats, out);
}